// round 3
// baseline (speedup 1.0000x reference)
#include <cuda_runtime.h>
#include <cuda_bf16.h>

// EEBasis: out[n, 0, s] = exp(-|zeta[s]| * sqrt(diffs[n, center_idxs[s], 3]))
// N = 262144 rows, 64 centers (float4: dx,dy,dz,r2), 256 shells (4/center).
//
// Float4-linear input index == float4-linear output index (shells are
// center-grouped). Both 256 MB streams are single-touch:
//  - __ldcs loads (evict-first), __stcs stores (streaming)
//  - 4 items/thread, split total/4 apart: all coalesced, loads front-batched
//    for MLP=4 so the LTS/DRAM request stream never starves.

__global__ void __launch_bounds__(256) eebasis_kernel(
    const float4* __restrict__ diffs,       // [N*64] float4
    const float4* __restrict__ zetas4,      // [64] float4 (256 zetas)
    const int*    __restrict__ center_idxs, // [256]
    float4*       __restrict__ out,         // [N*64] float4
    int quarter)                             // total/4
{
    int i0 = blockIdx.x * blockDim.x + threadIdx.x;
    if (i0 >= quarter) return;
    int i1 = i0 + quarter;
    int i2 = i1 + quarter;
    int i3 = i2 + quarter;

    int g0 = i0 & 63, n0 = i0 >> 6;
    int g1 = i1 & 63, n1 = i1 >> 6;
    int g2 = i2 & 63, n2 = i2 >> 6;
    int g3 = i3 & 63, n3 = i3 >> 6;

    // gather table (1KB, L1-resident)
    int c0 = __ldg(&center_idxs[4 * g0]);
    int c1 = __ldg(&center_idxs[4 * g1]);
    int c2 = __ldg(&center_idxs[4 * g2]);
    int c3 = __ldg(&center_idxs[4 * g3]);

    // front-batched streaming loads (MLP = 4)
    float4 d0 = __ldcs(&diffs[n0 * 64 + c0]);
    float4 d1 = __ldcs(&diffs[n1 * 64 + c1]);
    float4 d2 = __ldcs(&diffs[n2 * 64 + c2]);
    float4 d3 = __ldcs(&diffs[n3 * 64 + c3]);

    float4 z0 = __ldg(&zetas4[g0]);   // 1KB table, L1-resident
    float4 z1 = __ldg(&zetas4[g1]);
    float4 z2 = __ldg(&zetas4[g2]);
    float4 z3 = __ldg(&zetas4[g3]);

    float r0 = sqrtf(d0.w);
    float r1 = sqrtf(d1.w);
    float r2 = sqrtf(d2.w);
    float r3 = sqrtf(d3.w);

    float4 o0, o1, o2, o3;
    o0.x = __expf(-fabsf(z0.x) * r0);
    o0.y = __expf(-fabsf(z0.y) * r0);
    o0.z = __expf(-fabsf(z0.z) * r0);
    o0.w = __expf(-fabsf(z0.w) * r0);

    o1.x = __expf(-fabsf(z1.x) * r1);
    o1.y = __expf(-fabsf(z1.y) * r1);
    o1.z = __expf(-fabsf(z1.z) * r1);
    o1.w = __expf(-fabsf(z1.w) * r1);

    o2.x = __expf(-fabsf(z2.x) * r2);
    o2.y = __expf(-fabsf(z2.y) * r2);
    o2.z = __expf(-fabsf(z2.z) * r2);
    o2.w = __expf(-fabsf(z2.w) * r2);

    o3.x = __expf(-fabsf(z3.x) * r3);
    o3.y = __expf(-fabsf(z3.y) * r3);
    o3.z = __expf(-fabsf(z3.z) * r3);
    o3.w = __expf(-fabsf(z3.w) * r3);

    __stcs(&out[i0], o0);
    __stcs(&out[i1], o1);
    __stcs(&out[i2], o2);
    __stcs(&out[i3], o3);
}

extern "C" void kernel_launch(void* const* d_in, const int* in_sizes, int n_in,
                              void* d_out, int out_size)
{
    const float* diffs       = (const float*)d_in[0];  // [N, 64, 4] f32
    const float* zetas       = (const float*)d_in[1];  // [256] f32
    const int*   center_idxs = (const int*)  d_in[2];  // [256] i32

    int n_rows  = in_sizes[0] / (64 * 4);
    int total   = n_rows * 64;
    int quarter = total / 4;   // N is a power of two; divisible

    int threads = 256;
    int blocks  = (quarter + threads - 1) / threads;

    eebasis_kernel<<<blocks, threads>>>(
        (const float4*)diffs,
        (const float4*)zetas,
        center_idxs,
        (float4*)d_out,
        quarter);
}